// round 3
// baseline (speedup 1.0000x reference)
#include <cuda_runtime.h>
#include <math.h>

#define B_   8192
#define F_   32
#define P_   512
#define H_   256
#define BM   16        // rows per CTA
#define KC   32        // K-chunk for W1 staging
#define NT   256       // threads per CTA

#define SW_PITCH 257   // padded pitch for W1 chunk (conflict-free)

// dynamic smem layout (floats):
//   xn  : BM * P_          = 8192
//   sW  : KC * SW_PITCH    = 8224
//   red : BM * 8           = 128
#define SMEM_FLOATS (BM * P_ + KC * SW_PITCH + BM * 8)

__global__ __launch_bounds__(NT, 3)
void physchem_fused(const float* __restrict__ phys,
                    const float* __restrict__ ratios,
                    const int*   __restrict__ lengths,
                    const float* __restrict__ ln_gamma,
                    const float* __restrict__ ln_beta,
                    const float* __restrict__ W1,
                    const float* __restrict__ b1,
                    const float* __restrict__ W2,
                    const float* __restrict__ b2,
                    float*       __restrict__ out)
{
    extern __shared__ float sm[];
    float* xn  = sm;                        // [BM][P_]
    float* sW  = sm + BM * P_;              // [KC][SW_PITCH]
    float* red = sW + KC * SW_PITCH;        // [BM][8]

    const int tid  = threadIdx.x;
    const int wid  = tid >> 5;
    const int lane = tid & 31;
    const int b0   = blockIdx.x * BM;

    // ---------------- Phase A: ragged weighted mix + LayerNorm ----------------
    // 8 warps, each handles 2 rows. Lane l owns p-elements 4*(l + 32*i)+c.
    #pragma unroll
    for (int rr = 0; rr < 2; rr++) {
        const int r = wid * 2 + rr;
        const int b = b0 + r;
        const int len = lengths[b];

        // weight normalizer S = sum_{f<len} ratios[b,f]  (lane f holds one ratio)
        float rv = (lane < len) ? ratios[b * F_ + lane] : 0.0f;
        #pragma unroll
        for (int o = 16; o > 0; o >>= 1) rv += __shfl_xor_sync(0xffffffffu, rv, o);
        const float inv = 1.0f / (rv + 1e-8f);

        float acc[16];
        #pragma unroll
        for (int i = 0; i < 16; i++) acc[i] = 0.0f;

        const float* pb = phys + (size_t)b * (F_ * P_);
        for (int f = 0; f < len; f++) {
            const float w = ratios[b * F_ + f];            // uniform across warp
            const float4* pf = (const float4*)(pb + f * P_);
            #pragma unroll
            for (int i = 0; i < 4; i++) {
                float4 v = pf[lane + 32 * i];
                acc[4 * i + 0] += w * v.x;
                acc[4 * i + 1] += w * v.y;
                acc[4 * i + 2] += w * v.z;
                acc[4 * i + 3] += w * v.w;
            }
        }

        // normalize weights + LayerNorm stats
        float s = 0.0f, s2 = 0.0f;
        #pragma unroll
        for (int i = 0; i < 16; i++) {
            acc[i] *= inv;
            s  += acc[i];
            s2 += acc[i] * acc[i];
        }
        #pragma unroll
        for (int o = 16; o > 0; o >>= 1) {
            s  += __shfl_xor_sync(0xffffffffu, s,  o);
            s2 += __shfl_xor_sync(0xffffffffu, s2, o);
        }
        const float mu   = s * (1.0f / P_);
        const float var  = fmaxf(s2 * (1.0f / P_) - mu * mu, 0.0f);
        const float rstd = rsqrtf(var + 1e-5f);

        float4* xr = (float4*)(xn + r * P_);
        #pragma unroll
        for (int i = 0; i < 4; i++) {
            const int vi = lane + 32 * i;
            float4 g  = ((const float4*)ln_gamma)[vi];
            float4 be = ((const float4*)ln_beta)[vi];
            float4 o4;
            o4.x = (acc[4 * i + 0] - mu) * rstd * g.x + be.x;
            o4.y = (acc[4 * i + 1] - mu) * rstd * g.y + be.y;
            o4.z = (acc[4 * i + 2] - mu) * rstd * g.z + be.z;
            o4.w = (acc[4 * i + 3] - mu) * rstd * g.w + be.w;
            xr[vi] = o4;
        }
    }
    __syncthreads();

    // ---------------- Phase B: x @ W1^T via smem-staged K-chunks ----------------
    // thread tid owns output column j = tid for all BM rows.
    float hacc[BM];
    #pragma unroll
    for (int r = 0; r < BM; r++) hacc[r] = 0.0f;

    for (int kk = 0; kk < P_; kk += KC) {
        // load W1[:, kk:kk+KC] into sW[k][j] (transposed), float4 global reads
        {
            const int base = 4 * tid;                 // element within the 8192-elem chunk
            #pragma unroll
            for (int t = 0; t < (H_ * KC) / (NT * 4); t++) {   // 8 iters
                const int e = base + t * NT * 4;
                const int j = e >> 5;                 // 0..255
                const int k = e & 31;                 // multiple of 4
                float4 v = *(const float4*)(W1 + j * P_ + kk + k);
                sW[(k + 0) * SW_PITCH + j] = v.x;
                sW[(k + 1) * SW_PITCH + j] = v.y;
                sW[(k + 2) * SW_PITCH + j] = v.z;
                sW[(k + 3) * SW_PITCH + j] = v.w;
            }
        }
        __syncthreads();

        // cache this thread's W1 column chunk in registers
        float wreg[KC];
        #pragma unroll
        for (int k = 0; k < KC; k++) wreg[k] = sW[k * SW_PITCH + tid];

        #pragma unroll
        for (int r = 0; r < BM; r++) {
            const float4* xr = (const float4*)(xn + r * P_ + kk);
            float a = hacc[r];
            #pragma unroll
            for (int k4 = 0; k4 < KC / 4; k4++) {
                float4 v = xr[k4];                    // warp-uniform broadcast LDS.128
                a += v.x * wreg[4 * k4 + 0];
                a += v.y * wreg[4 * k4 + 1];
                a += v.z * wreg[4 * k4 + 2];
                a += v.w * wreg[4 * k4 + 3];
            }
            hacc[r] = a;
        }
        __syncthreads();
    }

    // ---------------- Epilogue: ReLU, dot with W2, reduce, nan_to_num ----------
    const float w2  = W2[tid];
    const float bb1 = b1[tid];
    #pragma unroll
    for (int r = 0; r < BM; r++) {
        float h = hacc[r] + bb1;
        h = fmaxf(h, 0.0f);
        float v = h * w2;
        #pragma unroll
        for (int o = 16; o > 0; o >>= 1) v += __shfl_xor_sync(0xffffffffu, v, o);
        if (lane == 0) red[r * 8 + wid] = v;
    }
    __syncthreads();

    if (tid < BM) {
        float y = b2[0];
        #pragma unroll
        for (int w = 0; w < 8; w++) y += red[tid * 8 + w];
        // jnp.nan_to_num: nan->0, +inf->FLT_MAX, -inf->-FLT_MAX
        if (isnan(y)) y = 0.0f;
        else if (isinf(y)) y = (y > 0.0f) ? 3.4028234663852886e38f : -3.4028234663852886e38f;
        out[b0 + tid] = y;
    }
}

extern "C" void kernel_launch(void* const* d_in, const int* in_sizes, int n_in,
                              void* d_out, int out_size)
{
    const float* phys     = (const float*)d_in[0];
    const float* ratios   = (const float*)d_in[1];
    const int*   lengths  = (const int*)  d_in[2];
    const float* ln_gamma = (const float*)d_in[3];
    const float* ln_beta  = (const float*)d_in[4];
    const float* W1       = (const float*)d_in[5];
    const float* b1       = (const float*)d_in[6];
    const float* W2       = (const float*)d_in[7];
    const float* b2       = (const float*)d_in[8];
    float* out = (float*)d_out;

    const int smem_bytes = SMEM_FLOATS * (int)sizeof(float);
    cudaFuncSetAttribute(physchem_fused,
                         cudaFuncAttributeMaxDynamicSharedMemorySize, smem_bytes);

    dim3 grid(B_ / BM);
    dim3 block(NT);
    physchem_fused<<<grid, block, smem_bytes>>>(
        phys, ratios, lengths, ln_gamma, ln_beta, W1, b1, W2, b2, out);
}

// round 4
// speedup vs baseline: 1.0391x; 1.0391x over previous
#include <cuda_runtime.h>
#include <math.h>

#define B_   8192
#define F_   32
#define P_   512
#define H_   256
#define BM   16        // rows per CTA
#define KC   32        // K-chunk for W1 staging
#define NT   256       // threads per CTA

#define PITCH2 257     // pitch (in float2) for paired-W1 smem chunk

// dynamic smem layout (floats):
//   xn    : BM * P_            = 8192   (32 KB)
//   sW2   : (KC/2) * PITCH2 *2 = 8224   (32.9 KB, float2 pairs)
//   wnorm : BM * F_            = 512    (2 KB)
//   red   : BM * 8             = 128
//   slen  : BM (ints)          = 16
#define SMEM_FLOATS (BM * P_ + (KC/2) * PITCH2 * 2 + BM * F_ + BM * 8 + BM)

// packed fp32x2 FMA: d.lo = a.lo*b.lo + c.lo ; d.hi = a.hi*b.hi + c.hi
__device__ __forceinline__ void ffma2(double& acc, double x, double w) {
    asm("fma.rn.f32x2 %0, %1, %2, %0;"
        : "+l"(*reinterpret_cast<unsigned long long*>(&acc))
        : "l"(*reinterpret_cast<unsigned long long*>(&x)),
          "l"(*reinterpret_cast<unsigned long long*>(&w)));
}

__global__ __launch_bounds__(NT, 3)
void physchem_fused(const float* __restrict__ phys,
                    const float* __restrict__ ratios,
                    const int*   __restrict__ lengths,
                    const float* __restrict__ ln_gamma,
                    const float* __restrict__ ln_beta,
                    const float* __restrict__ W1,
                    const float* __restrict__ b1,
                    const float* __restrict__ W2,
                    const float* __restrict__ b2,
                    float*       __restrict__ out)
{
    extern __shared__ float sm[];
    float*  xn    = sm;                                  // [BM][P_]
    float2* sW2   = (float2*)(sm + BM * P_);             // [KC/2][PITCH2] pairs
    float*  wnorm = sm + BM * P_ + (KC / 2) * PITCH2 * 2; // [BM][F_]
    float*  red   = wnorm + BM * F_;                     // [BM][8]
    int*    slen  = (int*)(red + BM * 8);                // [BM]

    const int tid  = threadIdx.x;
    const int wid  = tid >> 5;
    const int lane = tid & 31;
    const int b0   = blockIdx.x * BM;

    // ---------- Phase A0: normalized weights (warp w -> rows 2w, 2w+1) ----------
    #pragma unroll
    for (int rr = 0; rr < 2; rr++) {
        const int r = wid * 2 + rr;
        const int b = b0 + r;
        const int len = lengths[b];
        if (lane == 0) slen[r] = len;
        float rv = (lane < len) ? ratios[b * F_ + lane] : 0.0f;
        float s = rv;
        #pragma unroll
        for (int o = 16; o > 0; o >>= 1) s += __shfl_xor_sync(0xffffffffu, s, o);
        wnorm[r * F_ + lane] = rv / (s + 1e-8f);  // zero for lane >= len
    }
    __syncthreads();

    // ---------- Phase A1: weighted mix. Warp w owns p-slice [64w, 64w+64). ----------
    // Perfectly load-balanced: every warp does Sum(len) fragments of 256B loads.
    const int p2 = wid * 32 + lane;                 // float2 index within row
    for (int r = 0; r < BM; r++) {
        const int len = slen[r];
        const int b   = b0 + r;
        const float2* pp = (const float2*)phys + ((size_t)b * (F_ * P_) >> 1) + p2;
        const float* wr = wnorm + r * F_;
        float ax = 0.0f, ay = 0.0f;
        const int f4 = (len + 3) & ~3;              // wnorm is zero-padded past len
        for (int f = 0; f < f4; f += 4) {
            const float w0 = wr[f + 0];
            const float w1 = wr[f + 1];
            const float w2_ = wr[f + 2];
            const float w3 = wr[f + 3];
            float2 v0 = pp[(f + 0) * (P_ / 2)];
            float2 v1 = pp[(f + 1) * (P_ / 2)];
            float2 v2 = pp[(f + 2) * (P_ / 2)];
            float2 v3 = pp[(f + 3) * (P_ / 2)];
            ax += w0 * v0.x; ay += w0 * v0.y;
            ax += w1 * v1.x; ay += w1 * v1.y;
            ax += w2_ * v2.x; ay += w2_ * v2.y;
            ax += w3 * v3.x; ay += w3 * v3.y;
        }
        ((float2*)(xn + r * P_))[p2] = make_float2(ax, ay);
    }
    __syncthreads();

    // ---------- Phase A2: LayerNorm in-place (warp w -> rows 2w, 2w+1) ----------
    #pragma unroll
    for (int rr = 0; rr < 2; rr++) {
        const int r = wid * 2 + rr;
        float4 vv[4];
        float s = 0.0f, s2 = 0.0f;
        #pragma unroll
        for (int i = 0; i < 4; i++) {
            vv[i] = ((const float4*)(xn + r * P_))[lane + 32 * i];
            s  += vv[i].x + vv[i].y + vv[i].z + vv[i].w;
            s2 += vv[i].x * vv[i].x + vv[i].y * vv[i].y
                + vv[i].z * vv[i].z + vv[i].w * vv[i].w;
        }
        #pragma unroll
        for (int o = 16; o > 0; o >>= 1) {
            s  += __shfl_xor_sync(0xffffffffu, s,  o);
            s2 += __shfl_xor_sync(0xffffffffu, s2, o);
        }
        const float mu   = s * (1.0f / P_);
        const float var  = fmaxf(s2 * (1.0f / P_) - mu * mu, 0.0f);
        const float rstd = rsqrtf(var + 1e-5f);
        #pragma unroll
        for (int i = 0; i < 4; i++) {
            const int vi = lane + 32 * i;
            float4 g  = ((const float4*)ln_gamma)[vi];
            float4 be = ((const float4*)ln_beta)[vi];
            float4 o4;
            o4.x = (vv[i].x - mu) * rstd * g.x + be.x;
            o4.y = (vv[i].y - mu) * rstd * g.y + be.y;
            o4.z = (vv[i].z - mu) * rstd * g.z + be.z;
            o4.w = (vv[i].w - mu) * rstd * g.w + be.w;
            ((float4*)(xn + r * P_))[vi] = o4;
        }
    }
    __syncthreads();

    // ---------- Phase B: x @ W1^T with packed fp32x2 FMAs ----------
    // Thread tid owns output column j = tid. hacc2[r] holds 2 partial sums
    // (even-k / odd-k lanes of the f32x2), summed at the end.
    double hacc2[BM];
    #pragma unroll
    for (int r = 0; r < BM; r++) hacc2[r] = 0.0;   // bit pattern = two fp32 zeros

    for (int kk = 0; kk < P_; kk += KC) {
        // stage W1[:, kk:kk+KC] as k-pairs: sW2[kp][j] = (W1[j][2kp], W1[j][2kp+1])
        {
            const int base = 4 * tid;
            #pragma unroll
            for (int t = 0; t < (H_ * KC) / (NT * 4); t++) {   // 8 iters
                const int e = base + t * NT * 4;
                const int j = e >> 5;                 // 0..255
                const int k = e & 31;                 // multiple of 4
                float4 v = *(const float4*)(W1 + j * P_ + kk + k);
                float2* dst = sW2 + (k >> 1) * PITCH2 + j;
                dst[0]      = make_float2(v.x, v.y);
                dst[PITCH2] = make_float2(v.z, v.w);
            }
        }
        __syncthreads();

        // this thread's 16 weight pairs for the chunk
        double wreg[KC / 2];
        #pragma unroll
        for (int kp = 0; kp < KC / 2; kp++)
            wreg[kp] = *(const double*)(sW2 + kp * PITCH2 + tid);

        #pragma unroll
        for (int r = 0; r < BM; r++) {
            const double2* xr = (const double2*)(xn + r * P_ + kk);
            #pragma unroll
            for (int q = 0; q < KC / 4; q++) {        // 8 x LDS.128 (broadcast)
                double2 v = xr[q];                     // 4 floats = 2 pairs
                ffma2(hacc2[r], v.x, wreg[2 * q]);
                ffma2(hacc2[r], v.y, wreg[2 * q + 1]);
            }
        }
        __syncthreads();
    }

    // ---------- Epilogue: ReLU, dot with W2, reduce, nan_to_num ----------
    const float w2  = W2[tid];
    const float bb1 = b1[tid];
    #pragma unroll
    for (int r = 0; r < BM; r++) {
        float2 p = *reinterpret_cast<float2*>(&hacc2[r]);
        float h = p.x + p.y + bb1;
        h = fmaxf(h, 0.0f);
        float v = h * w2;
        #pragma unroll
        for (int o = 16; o > 0; o >>= 1) v += __shfl_xor_sync(0xffffffffu, v, o);
        if (lane == 0) red[r * 8 + wid] = v;
    }
    __syncthreads();

    if (tid < BM) {
        float y = b2[0];
        #pragma unroll
        for (int w = 0; w < 8; w++) y += red[tid * 8 + w];
        if (isnan(y)) y = 0.0f;
        else if (isinf(y)) y = (y > 0.0f) ? 3.4028234663852886e38f : -3.4028234663852886e38f;
        out[b0 + tid] = y;
    }
}

extern "C" void kernel_launch(void* const* d_in, const int* in_sizes, int n_in,
                              void* d_out, int out_size)
{
    const float* phys     = (const float*)d_in[0];
    const float* ratios   = (const float*)d_in[1];
    const int*   lengths  = (const int*)  d_in[2];
    const float* ln_gamma = (const float*)d_in[3];
    const float* ln_beta  = (const float*)d_in[4];
    const float* W1       = (const float*)d_in[5];
    const float* b1       = (const float*)d_in[6];
    const float* W2       = (const float*)d_in[7];
    const float* b2       = (const float*)d_in[8];
    float* out = (float*)d_out;

    const int smem_bytes = SMEM_FLOATS * (int)sizeof(float);
    cudaFuncSetAttribute(physchem_fused,
                         cudaFuncAttributeMaxDynamicSharedMemorySize, smem_bytes);

    dim3 grid(B_ / BM);
    dim3 block(NT);
    physchem_fused<<<grid, block, smem_bytes>>>(
        phys, ratios, lengths, ln_gamma, ln_beta, W1, b1, W2, b2, out);
}